// round 2
// baseline (speedup 1.0000x reference)
#include <cuda_runtime.h>
#include <math.h>

// ---------------- scratch (device globals: allocation-free) ----------------
__device__ float g_Kt [64u*128u*960u];       // 31.5 MB
__device__ float g_KVt[64u*128u*960u];       // 31.5 MB
__device__ float g_Qt [64u*128u*512u];       // 16.8 MB (per-branch reuse)
__device__ float g_S  [64u*512u*960u];       // 125.8 MB (per-branch reuse)
__device__ float g_O  [8u*1024u*512u];       // 16.8 MB (per-branch reuse)
__device__ float g_stats[128];               // (mean, rstd) per bh

// ---------------- GEMM NT: C[m,n] = alpha * sum_k A[m,k]*B[n,k] ----------------
// A: [M,K] row-major (lda), B: [N,K] row-major (ldb), C: [M,N] row-major (ldc)
// batch z: A += z*aStride, B += (z & bMask)*bStride, C += z*cStride
template<int BM, int BN, int BK, int TM, int TN>
__global__ void __launch_bounds__((BM/TM)*(BN/TN))
gemm_nt(const float* __restrict__ A, const float* __restrict__ B, float* __restrict__ C,
        int K, int lda, int ldb, int ldc,
        long aStride, long bStride, int bMask, long cStride, float alpha)
{
    constexpr int THREADS = (BM/TM)*(BN/TN);
    constexpr int PAD = 4;
    __shared__ float As[BK][BM+PAD];
    __shared__ float Bs[BK][BN+PAD];

    const int batch = blockIdx.z;
    A += (long)batch * aStride;
    B += (long)(batch & bMask) * bStride;
    C += (long)batch * cStride;

    const int m0 = blockIdx.y * BM;
    const int n0 = blockIdx.x * BN;
    const int tid = threadIdx.x;
    const int tx = tid % (BN/TN);
    const int ty = tid / (BN/TN);

    float acc[TM][TN];
#pragma unroll
    for (int i = 0; i < TM; i++)
#pragma unroll
        for (int j = 0; j < TN; j++) acc[i][j] = 0.f;

    for (int k0 = 0; k0 < K; k0 += BK) {
        constexpr int AF4 = BM*BK/4;
#pragma unroll
        for (int it = 0; it < AF4/THREADS; it++) {
            int idx = tid + it*THREADS;
            int kq = idx % (BK/4);
            int m  = idx / (BK/4);
            float4 v = *reinterpret_cast<const float4*>(&A[(long)(m0+m)*lda + k0 + kq*4]);
            As[kq*4+0][m] = v.x; As[kq*4+1][m] = v.y;
            As[kq*4+2][m] = v.z; As[kq*4+3][m] = v.w;
        }
        constexpr int BF4 = BN*BK/4;
#pragma unroll
        for (int it = 0; it < BF4/THREADS; it++) {
            int idx = tid + it*THREADS;
            int kq = idx % (BK/4);
            int nn = idx / (BK/4);
            float4 v = *reinterpret_cast<const float4*>(&B[(long)(n0+nn)*ldb + k0 + kq*4]);
            Bs[kq*4+0][nn] = v.x; Bs[kq*4+1][nn] = v.y;
            Bs[kq*4+2][nn] = v.z; Bs[kq*4+3][nn] = v.w;
        }
        __syncthreads();
#pragma unroll
        for (int k = 0; k < BK; k++) {
            float ra[TM], rb[TN];
#pragma unroll
            for (int i = 0; i < TM; i++) ra[i] = As[k][ty*TM+i];
#pragma unroll
            for (int j = 0; j < TN; j++) rb[j] = Bs[k][tx*TN+j];
#pragma unroll
            for (int i = 0; i < TM; i++)
#pragma unroll
                for (int j = 0; j < TN; j++) acc[i][j] += ra[i]*rb[j];
        }
        __syncthreads();
    }
#pragma unroll
    for (int i = 0; i < TM; i++) {
#pragma unroll
        for (int j4 = 0; j4 < TN/4; j4++) {
            float4 v;
            v.x = alpha*acc[i][j4*4+0];
            v.y = alpha*acc[i][j4*4+1];
            v.z = alpha*acc[i][j4*4+2];
            v.w = alpha*acc[i][j4*4+3];
            *reinterpret_cast<float4*>(&C[(long)(m0+ty*TM+i)*ldc + n0 + tx*TN + j4*4]) = v;
        }
    }
}

// ---------------- GEMM TN: C[m,n] = alpha * sum_k A[k,m]*B[k,n] ----------------
// A: [K,M] row-major (lda), B: [K,N] row-major (ldb)
template<int BM, int BN, int BK, int TM, int TN>
__global__ void __launch_bounds__((BM/TM)*(BN/TN))
gemm_tn(const float* __restrict__ A, const float* __restrict__ B, float* __restrict__ C,
        int K, int lda, int ldb, int ldc,
        long aStride, long bStride, int bMask, long cStride, float alpha)
{
    constexpr int THREADS = (BM/TM)*(BN/TN);
    constexpr int PAD = 4;
    __shared__ float As[BK][BM+PAD];
    __shared__ float Bs[BK][BN+PAD];

    const int batch = blockIdx.z;
    A += (long)batch * aStride;
    B += (long)(batch & bMask) * bStride;
    C += (long)batch * cStride;

    const int m0 = blockIdx.y * BM;
    const int n0 = blockIdx.x * BN;
    const int tid = threadIdx.x;
    const int tx = tid % (BN/TN);
    const int ty = tid / (BN/TN);

    float acc[TM][TN];
#pragma unroll
    for (int i = 0; i < TM; i++)
#pragma unroll
        for (int j = 0; j < TN; j++) acc[i][j] = 0.f;

    for (int k0 = 0; k0 < K; k0 += BK) {
        constexpr int AF4 = BM*BK/4;
#pragma unroll
        for (int it = 0; it < AF4/THREADS; it++) {
            int idx = tid + it*THREADS;
            int mq = idx % (BM/4);
            int k  = idx / (BM/4);
            float4 v = *reinterpret_cast<const float4*>(&A[(long)(k0+k)*lda + m0 + mq*4]);
            *reinterpret_cast<float4*>(&As[k][mq*4]) = v;
        }
        constexpr int BF4 = BN*BK/4;
#pragma unroll
        for (int it = 0; it < BF4/THREADS; it++) {
            int idx = tid + it*THREADS;
            int nq = idx % (BN/4);
            int k  = idx / (BN/4);
            float4 v = *reinterpret_cast<const float4*>(&B[(long)(k0+k)*ldb + n0 + nq*4]);
            *reinterpret_cast<float4*>(&Bs[k][nq*4]) = v;
        }
        __syncthreads();
#pragma unroll
        for (int k = 0; k < BK; k++) {
            float ra[TM], rb[TN];
#pragma unroll
            for (int i = 0; i < TM; i++) ra[i] = As[k][ty*TM+i];
#pragma unroll
            for (int j = 0; j < TN; j++) rb[j] = Bs[k][tx*TN+j];
#pragma unroll
            for (int i = 0; i < TM; i++)
#pragma unroll
                for (int j = 0; j < TN; j++) acc[i][j] += ra[i]*rb[j];
        }
        __syncthreads();
    }
#pragma unroll
    for (int i = 0; i < TM; i++) {
#pragma unroll
        for (int j4 = 0; j4 < TN/4; j4++) {
            float4 v;
            v.x = alpha*acc[i][j4*4+0];
            v.y = alpha*acc[i][j4*4+1];
            v.z = alpha*acc[i][j4*4+2];
            v.w = alpha*acc[i][j4*4+3];
            *reinterpret_cast<float4*>(&C[(long)(m0+ty*TM+i)*ldc + n0 + tx*TN + j4*4]) = v;
        }
    }
}

// ---------------- InstanceNorm stats: mean & rstd over [Cq,960] per bh ----------------
__global__ void inorm_stats(const float* __restrict__ S, float* __restrict__ stats, int elems)
{
    const int b = blockIdx.x;
    const float4* p = reinterpret_cast<const float4*>(S + (long)b * elems);
    const int n4 = elems >> 2;
    float s = 0.f, ss = 0.f;
    for (int i = threadIdx.x; i < n4; i += blockDim.x) {
        float4 v = p[i];
        s  += v.x + v.y + v.z + v.w;
        ss += v.x*v.x + v.y*v.y + v.z*v.z + v.w*v.w;
    }
    __shared__ float sh1[256], sh2[256];
    sh1[threadIdx.x] = s; sh2[threadIdx.x] = ss;
    __syncthreads();
    for (int o = 128; o > 0; o >>= 1) {
        if (threadIdx.x < o) {
            sh1[threadIdx.x] += sh1[threadIdx.x + o];
            sh2[threadIdx.x] += sh2[threadIdx.x + o];
        }
        __syncthreads();
    }
    if (threadIdx.x == 0) {
        float inv = 1.f / (float)elems;
        float m = sh1[0] * inv;
        float var = sh2[0] * inv - m*m;
        stats[2*b]   = m;
        stats[2*b+1] = rsqrtf(var + 1e-5f);
    }
}

// ---------------- per-row inorm apply + softmax over 960 (in place) ----------------
__global__ void inorm_softmax(float* __restrict__ S, const float* __restrict__ stats, int rowsPerBatch)
{
    const int row = blockIdx.x;
    const int bh = row / rowsPerBatch;
    float* p = S + (long)row * 960;
    const int tid = threadIdx.x;          // 256 threads, 240 active (240*4 = 960)
    const bool act = tid < 240;
    const float mean = stats[2*bh], rstd = stats[2*bh+1];

    float4 v = make_float4(0.f, 0.f, 0.f, 0.f);
    if (act) v = *reinterpret_cast<float4*>(&p[tid*4]);
    v.x = (v.x - mean)*rstd; v.y = (v.y - mean)*rstd;
    v.z = (v.z - mean)*rstd; v.w = (v.w - mean)*rstd;

    __shared__ float sh[256];
    float mx = act ? fmaxf(fmaxf(v.x, v.y), fmaxf(v.z, v.w)) : -1e30f;
    sh[tid] = mx; __syncthreads();
    for (int o = 128; o > 0; o >>= 1) {
        if (tid < o) sh[tid] = fmaxf(sh[tid], sh[tid + o]);
        __syncthreads();
    }
    mx = sh[0]; __syncthreads();

    float4 e;
    e.x = __expf(v.x - mx); e.y = __expf(v.y - mx);
    e.z = __expf(v.z - mx); e.w = __expf(v.w - mx);
    float s = act ? (e.x + e.y + e.z + e.w) : 0.f;
    sh[tid] = s; __syncthreads();
    for (int o = 128; o > 0; o >>= 1) {
        if (tid < o) sh[tid] += sh[tid + o];
        __syncthreads();
    }
    const float inv = 1.f / sh[0];
    if (act) {
        e.x *= inv; e.y *= inv; e.z *= inv; e.w *= inv;
        *reinterpret_cast<float4*>(&p[tid*4]) = e;
    }
}

// ---------------- host-side dispatch ----------------
static void launch_nt(const float* A, const float* B, float* C,
                      int M, int N, int K, int lda, int ldb, int ldc,
                      long aS, long bS, int bMask, long cS, float alpha, int batch)
{
    if (M % 128 == 0) {
        dim3 g(N/64, M/128, batch);
        gemm_nt<128,64,16,8,8><<<g, 128>>>(A, B, C, K, lda, ldb, ldc, aS, bS, bMask, cS, alpha);
    } else {
        dim3 g(N/64, M/64, batch);
        gemm_nt<64,64,16,8,8><<<g, 64>>>(A, B, C, K, lda, ldb, ldc, aS, bS, bMask, cS, alpha);
    }
}

static void launch_tn(const float* A, const float* B, float* C,
                      int M, int N, int K, int lda, int ldb, int ldc,
                      long aS, long bS, int bMask, long cS, float alpha, int batch)
{
    if (M % 128 == 0) {
        dim3 g(N/64, M/128, batch);
        gemm_tn<128,64,16,8,8><<<g, 128>>>(A, B, C, K, lda, ldb, ldc, aS, bS, bMask, cS, alpha);
    } else {
        dim3 g(N/64, M/64, batch);
        gemm_tn<64,64,16,8,8><<<g, 64>>>(A, B, C, K, lda, ldb, ldc, aS, bS, bMask, cS, alpha);
    }
}

extern "C" void kernel_launch(void* const* d_in, const int* in_sizes, int n_in,
                              void* d_out, int out_size)
{
    const float* Q[4]  = {(const float*)d_in[0], (const float*)d_in[1],
                          (const float*)d_in[2], (const float*)d_in[3]};
    const float* KV    = (const float*)d_in[4];
    const float* Wk    = (const float*)d_in[5];
    const float* Wv    = (const float*)d_in[6];
    const float* Wq[4] = {(const float*)d_in[7], (const float*)d_in[8],
                          (const float*)d_in[9], (const float*)d_in[10]};
    const float* Wo[4] = {(const float*)d_in[11], (const float*)d_in[12],
                          (const float*)d_in[13], (const float*)d_in[14]};
    float* out = (float*)d_out;

    float *Kt, *KVt, *Qt, *S, *O, *stats;
    cudaGetSymbolAddress((void**)&Kt,    g_Kt);
    cudaGetSymbolAddress((void**)&KVt,   g_KVt);
    cudaGetSymbolAddress((void**)&Qt,    g_Qt);
    cudaGetSymbolAddress((void**)&S,     g_S);
    cudaGetSymbolAddress((void**)&O,     g_O);
    cudaGetSymbolAddress((void**)&stats, g_stats);

    const float inv_scale = 1.0f / sqrtf(960.0f);

    // Kt = KV @ Wk^T    (per bh slice, head-indexed weights)
    launch_nt(KV, Wk, Kt, 128, 960, 960, 960, 960, 960,
              128L*960, 960L*960, 7, 128L*960, 1.f, 64);
    // KVt = Kt @ Wv^T   (shared K == V)
    launch_nt(Kt, Wv, KVt, 128, 960, 960, 960, 960, 960,
              128L*960, 960L*960, 7, 128L*960, 1.f, 64);

    const int Cqs[4] = {64, 128, 256, 512};
    long outOff = 0;
    for (int br = 0; br < 4; br++) {
        const int Cq = Cqs[br];
        // Qt = Q @ Wq^T
        launch_nt(Q[br], Wq[br], Qt, 128, Cq, Cq, Cq, Cq, Cq,
                  128L*Cq, (long)Cq*Cq, 7, 128L*Cq, 1.f, 64);
        // S[c,s] = inv_scale * sum_n Qt[n,c] * KVt[n,s]    (TN)
        launch_tn(Qt, KVt, S, Cq, 960, 128, Cq, 960, 960,
                  128L*Cq, 128L*960, 63, (long)Cq*960, inv_scale, 64);
        // InstanceNorm stats per (b,h), then row softmax in place
        inorm_stats<<<64, 256>>>(S, stats, Cq*960);
        inorm_softmax<<<64*Cq, 256>>>(S, stats, Cq);
        // outp[n,c] = sum_s KVt[n,s] * P[c,s]  -> lands contiguous as [B, N, Cq]
        launch_nt(KVt, S, O, 128, Cq, 960, 960, 960, Cq,
                  128L*960, (long)Cq*960, 63, 128L*Cq, 1.f, 64);
        // Y = outp @ Wo^T  (single GEMM, M = B*N = 8192)
        launch_nt(O, Wo[br], out + outOff, 8192, Cq, Cq, Cq, Cq, Cq,
                  0, 0, 0, 0, 1.f, 1);
        outOff += 8192L * Cq;
    }
}

// round 3
// speedup vs baseline: 1.7606x; 1.7606x over previous
#include <cuda_runtime.h>
#include <cuda_bf16.h>
#include <math.h>
#include <stdint.h>

// ---------------- scratch (device globals: allocation-free) ----------------
__device__ float g_Kt [64u*128u*960u];       // Kt, then reused as KVtT [64][960][128]
__device__ float g_KVt[64u*128u*960u];       // KVt [64][128][960]
__device__ float g_Qt [64u*128u*512u];       // QtT [64][Cq][128]
__device__ float g_S  [64u*512u*960u];       // S   [64][Cq][960]
__device__ float g_O  [8u*1024u*512u];       // O   [B,N,Cq]
__device__ float g_stats[128];               // (mean, rstd) per bh

// ---------------- bf16 mma helper ----------------
__device__ __forceinline__ void mma_bf16(float* c, const uint32_t* a, const uint32_t* b)
{
    asm volatile(
        "mma.sync.aligned.m16n8k16.row.col.f32.bf16.bf16.f32 "
        "{%0,%1,%2,%3}, {%4,%5,%6,%7}, {%8,%9}, {%0,%1,%2,%3};"
        : "+f"(c[0]), "+f"(c[1]), "+f"(c[2]), "+f"(c[3])
        : "r"(a[0]), "r"(a[1]), "r"(a[2]), "r"(a[3]), "r"(b[0]), "r"(b[1]));
}

// ---------------- NT GEMM via bf16 tensor cores, 2-way split (3 products) ----
// C[m,n] = alpha * sum_k A[m,k]*B[n,k]
// A: [M,K] row-major (lda), B: [N,K] row-major (ldb), C row-major (ldc)
// batch z: A += (z&aMask)*aS, B += (z&bMask)*bS, C += z*cS
// Requires: M % BM == 0, N % BN == 0, K % BK == 0 (all true for this problem)
template<int BM, int BN, int BK>
__global__ void __launch_bounds__(128)
gemm_nt_mma(const float* __restrict__ A, const float* __restrict__ B, float* __restrict__ C,
            int K, int lda, int ldb, int ldc,
            long aS, int aMask, long bS, int bMask, long cS, float alpha)
{
    constexpr int PADK = BK + 8;                 // 40 bf16 = 80B row stride (conflict-free)
    __shared__ __nv_bfloat16 Ah[BM][PADK], Al[BM][PADK];
    __shared__ __nv_bfloat16 Bh[BN][PADK], Bl[BN][PADK];

    const int z = blockIdx.z;
    A += (long)(z & aMask) * aS;
    B += (long)(z & bMask) * bS;
    C += (long)z * cS;

    const int m0 = blockIdx.y * BM, n0 = blockIdx.x * BN;
    const int tid = threadIdx.x, lane = tid & 31, warp = tid >> 5;
    const int wy = warp >> 1, wx = warp & 1;     // 2x2 warps
    constexpr int WM = BM / 2, WN = BN / 2;
    constexpr int MT = WM / 16, NT = WN / 8;
    const int m0w = wy * WM, n0w = wx * WN;
    const int r = lane >> 2, p = lane & 3;

    float acc[MT][NT][4];
#pragma unroll
    for (int mt = 0; mt < MT; mt++)
#pragma unroll
        for (int nt = 0; nt < NT; nt++)
#pragma unroll
            for (int i = 0; i < 4; i++) acc[mt][nt][i] = 0.f;

    for (int k0 = 0; k0 < K; k0 += BK) {
        // ---- stage A tile (BM x BK fp32 -> hi/lo bf16) ----
        constexpr int AV = BM * BK / 4;          // float4 count
#pragma unroll
        for (int it = 0; it < AV / 128; it++) {
            int idx = tid + it * 128;
            int kq  = idx & 7;                   // BK/4 = 8 quads per row
            int m   = idx >> 3;
            float4 v = *reinterpret_cast<const float4*>(&A[(long)(m0 + m) * lda + k0 + kq * 4]);
            __nv_bfloat162 h01, h23, l01, l23;
            h01.x = __float2bfloat16(v.x); h01.y = __float2bfloat16(v.y);
            h23.x = __float2bfloat16(v.z); h23.y = __float2bfloat16(v.w);
            l01.x = __float2bfloat16(v.x - __bfloat162float(h01.x));
            l01.y = __float2bfloat16(v.y - __bfloat162float(h01.y));
            l23.x = __float2bfloat16(v.z - __bfloat162float(h23.x));
            l23.y = __float2bfloat16(v.w - __bfloat162float(h23.y));
            *reinterpret_cast<__nv_bfloat162*>(&Ah[m][kq * 4])     = h01;
            *reinterpret_cast<__nv_bfloat162*>(&Ah[m][kq * 4 + 2]) = h23;
            *reinterpret_cast<__nv_bfloat162*>(&Al[m][kq * 4])     = l01;
            *reinterpret_cast<__nv_bfloat162*>(&Al[m][kq * 4 + 2]) = l23;
        }
        // ---- stage B tile (BN x BK) ----
        constexpr int BV = BN * BK / 4;
#pragma unroll
        for (int it = 0; it < BV / 128; it++) {
            int idx = tid + it * 128;
            int kq  = idx & 7;
            int n   = idx >> 3;
            float4 v = *reinterpret_cast<const float4*>(&B[(long)(n0 + n) * ldb + k0 + kq * 4]);
            __nv_bfloat162 h01, h23, l01, l23;
            h01.x = __float2bfloat16(v.x); h01.y = __float2bfloat16(v.y);
            h23.x = __float2bfloat16(v.z); h23.y = __float2bfloat16(v.w);
            l01.x = __float2bfloat16(v.x - __bfloat162float(h01.x));
            l01.y = __float2bfloat16(v.y - __bfloat162float(h01.y));
            l23.x = __float2bfloat16(v.z - __bfloat162float(h23.x));
            l23.y = __float2bfloat16(v.w - __bfloat162float(h23.y));
            *reinterpret_cast<__nv_bfloat162*>(&Bh[n][kq * 4])     = h01;
            *reinterpret_cast<__nv_bfloat162*>(&Bh[n][kq * 4 + 2]) = h23;
            *reinterpret_cast<__nv_bfloat162*>(&Bl[n][kq * 4])     = l01;
            *reinterpret_cast<__nv_bfloat162*>(&Bl[n][kq * 4 + 2]) = l23;
        }
        __syncthreads();

#pragma unroll
        for (int ks = 0; ks < BK; ks += 16) {
            uint32_t ah[MT][4], al[MT][4], bh[NT][2], bl[NT][2];
#pragma unroll
            for (int mt = 0; mt < MT; mt++) {
                int row = m0w + mt * 16 + r;
                ah[mt][0] = *reinterpret_cast<const uint32_t*>(&Ah[row    ][ks + 2 * p]);
                ah[mt][1] = *reinterpret_cast<const uint32_t*>(&Ah[row + 8][ks + 2 * p]);
                ah[mt][2] = *reinterpret_cast<const uint32_t*>(&Ah[row    ][ks + 2 * p + 8]);
                ah[mt][3] = *reinterpret_cast<const uint32_t*>(&Ah[row + 8][ks + 2 * p + 8]);
                al[mt][0] = *reinterpret_cast<const uint32_t*>(&Al[row    ][ks + 2 * p]);
                al[mt][1] = *reinterpret_cast<const uint32_t*>(&Al[row + 8][ks + 2 * p]);
                al[mt][2] = *reinterpret_cast<const uint32_t*>(&Al[row    ][ks + 2 * p + 8]);
                al[mt][3] = *reinterpret_cast<const uint32_t*>(&Al[row + 8][ks + 2 * p + 8]);
            }
#pragma unroll
            for (int nt = 0; nt < NT; nt++) {
                int nrow = n0w + nt * 8 + r;
                bh[nt][0] = *reinterpret_cast<const uint32_t*>(&Bh[nrow][ks + 2 * p]);
                bh[nt][1] = *reinterpret_cast<const uint32_t*>(&Bh[nrow][ks + 2 * p + 8]);
                bl[nt][0] = *reinterpret_cast<const uint32_t*>(&Bl[nrow][ks + 2 * p]);
                bl[nt][1] = *reinterpret_cast<const uint32_t*>(&Bl[nrow][ks + 2 * p + 8]);
            }
#pragma unroll
            for (int mt = 0; mt < MT; mt++)
#pragma unroll
                for (int nt = 0; nt < NT; nt++) {
                    mma_bf16(acc[mt][nt], ah[mt], bh[nt]);   // hi*hi
                    mma_bf16(acc[mt][nt], ah[mt], bl[nt]);   // hi*lo
                    mma_bf16(acc[mt][nt], al[mt], bh[nt]);   // lo*hi
                }
        }
        __syncthreads();
    }

    // ---- epilogue ----
#pragma unroll
    for (int mt = 0; mt < MT; mt++) {
        int row = m0 + m0w + mt * 16 + r;
#pragma unroll
        for (int nt = 0; nt < NT; nt++) {
            int col = n0 + n0w + nt * 8 + 2 * p;
            float2 v0, v1;
            v0.x = alpha * acc[mt][nt][0]; v0.y = alpha * acc[mt][nt][1];
            v1.x = alpha * acc[mt][nt][2]; v1.y = alpha * acc[mt][nt][3];
            *reinterpret_cast<float2*>(&C[(long)row * ldc + col])       = v0;
            *reinterpret_cast<float2*>(&C[(long)(row + 8) * ldc + col]) = v1;
        }
    }
}

// ---------------- transpose: [batch][128][960] -> [batch][960][128] ----------
__global__ void transpose_kvt(const float* __restrict__ in, float* __restrict__ out)
{
    __shared__ float t[32][33];
    const int b = blockIdx.z;
    const int s0 = blockIdx.x * 32, n0 = blockIdx.y * 32;
    in  += (long)b * 128 * 960;
    out += (long)b * 960 * 128;
    const int tx = threadIdx.x, ty = threadIdx.y;
#pragma unroll
    for (int i = 0; i < 4; i++)
        t[ty + 8 * i][tx] = in[(long)(n0 + ty + 8 * i) * 960 + s0 + tx];
    __syncthreads();
#pragma unroll
    for (int i = 0; i < 4; i++)
        out[(long)(s0 + ty + 8 * i) * 128 + n0 + tx] = t[tx][ty + 8 * i];
}

// ---------------- InstanceNorm stats: mean & rstd over [Cq,960] per bh --------
__global__ void inorm_stats(const float* __restrict__ S, float* __restrict__ stats, int elems)
{
    const int b = blockIdx.x;
    const float4* p = reinterpret_cast<const float4*>(S + (long)b * elems);
    const int n4 = elems >> 2;
    float s = 0.f, ss = 0.f;
    for (int i = threadIdx.x; i < n4; i += blockDim.x) {
        float4 v = p[i];
        s  += v.x + v.y + v.z + v.w;
        ss += v.x * v.x + v.y * v.y + v.z * v.z + v.w * v.w;
    }
    __shared__ float sh1[1024], sh2[1024];
    sh1[threadIdx.x] = s; sh2[threadIdx.x] = ss;
    __syncthreads();
    for (int o = blockDim.x >> 1; o > 0; o >>= 1) {
        if (threadIdx.x < o) {
            sh1[threadIdx.x] += sh1[threadIdx.x + o];
            sh2[threadIdx.x] += sh2[threadIdx.x + o];
        }
        __syncthreads();
    }
    if (threadIdx.x == 0) {
        float inv = 1.f / (float)elems;
        float m = sh1[0] * inv;
        float var = sh2[0] * inv - m * m;
        stats[2 * b]     = m;
        stats[2 * b + 1] = rsqrtf(var + 1e-5f);
    }
}

// ---------------- per-row inorm apply + softmax over 960 (in place) -----------
__global__ void inorm_softmax(float* __restrict__ S, const float* __restrict__ stats, int rowsPerBatch)
{
    const int row = blockIdx.x;
    const int bh = row / rowsPerBatch;
    float* p = S + (long)row * 960;
    const int tid = threadIdx.x;          // 256 threads, 240 active (240*4 = 960)
    const bool act = tid < 240;
    const float mean = stats[2 * bh], rstd = stats[2 * bh + 1];

    float4 v = make_float4(0.f, 0.f, 0.f, 0.f);
    if (act) v = *reinterpret_cast<float4*>(&p[tid * 4]);
    v.x = (v.x - mean) * rstd; v.y = (v.y - mean) * rstd;
    v.z = (v.z - mean) * rstd; v.w = (v.w - mean) * rstd;

    __shared__ float sh[256];
    float mx = act ? fmaxf(fmaxf(v.x, v.y), fmaxf(v.z, v.w)) : -1e30f;
    sh[tid] = mx; __syncthreads();
    for (int o = 128; o > 0; o >>= 1) {
        if (tid < o) sh[tid] = fmaxf(sh[tid], sh[tid + o]);
        __syncthreads();
    }
    mx = sh[0]; __syncthreads();

    float4 e;
    e.x = __expf(v.x - mx); e.y = __expf(v.y - mx);
    e.z = __expf(v.z - mx); e.w = __expf(v.w - mx);
    float s = act ? (e.x + e.y + e.z + e.w) : 0.f;
    sh[tid] = s; __syncthreads();
    for (int o = 128; o > 0; o >>= 1) {
        if (tid < o) sh[tid] += sh[tid + o];
        __syncthreads();
    }
    const float inv = 1.f / sh[0];
    if (act) {
        e.x *= inv; e.y *= inv; e.z *= inv; e.w *= inv;
        *reinterpret_cast<float4*>(&p[tid * 4]) = e;
    }
}

// ---------------- host-side dispatch ----------------
static void mma_nt(const float* A, const float* B, float* C,
                   int M, int N, int K, int lda, int ldb, int ldc,
                   long aS, int aMask, long bS, int bMask, long cS,
                   float alpha, int batch)
{
    if (M % 128 == 0) {
        dim3 g(N / 64, M / 128, batch);
        gemm_nt_mma<128, 64, 32><<<g, 128>>>(A, B, C, K, lda, ldb, ldc,
                                             aS, aMask, bS, bMask, cS, alpha);
    } else {
        dim3 g(N / 64, M / 64, batch);
        gemm_nt_mma<64, 64, 32><<<g, 128>>>(A, B, C, K, lda, ldb, ldc,
                                            aS, aMask, bS, bMask, cS, alpha);
    }
}

extern "C" void kernel_launch(void* const* d_in, const int* in_sizes, int n_in,
                              void* d_out, int out_size)
{
    const float* Q[4]  = {(const float*)d_in[0], (const float*)d_in[1],
                          (const float*)d_in[2], (const float*)d_in[3]};
    const float* KV    = (const float*)d_in[4];
    const float* Wk    = (const float*)d_in[5];
    const float* Wv    = (const float*)d_in[6];
    const float* Wq[4] = {(const float*)d_in[7], (const float*)d_in[8],
                          (const float*)d_in[9], (const float*)d_in[10]};
    const float* Wo[4] = {(const float*)d_in[11], (const float*)d_in[12],
                          (const float*)d_in[13], (const float*)d_in[14]};
    float* out = (float*)d_out;

    float *Kt, *KVt, *QtT, *S, *O, *stats;
    cudaGetSymbolAddress((void**)&Kt,    g_Kt);
    cudaGetSymbolAddress((void**)&KVt,   g_KVt);
    cudaGetSymbolAddress((void**)&QtT,   g_Qt);
    cudaGetSymbolAddress((void**)&S,     g_S);
    cudaGetSymbolAddress((void**)&O,     g_O);
    cudaGetSymbolAddress((void**)&stats, g_stats);

    const int FULL = 0x7FFFFFFF;
    const float inv_scale = 1.0f / sqrtf(960.0f);

    // Kt = KV @ Wk^T    (per-bh slice, head-indexed weights)
    mma_nt(KV, Wk, Kt, 128, 960, 960, 960, 960, 960,
           128L * 960, FULL, 960L * 960, 7, 128L * 960, 1.f, 64);
    // KVt = Kt @ Wv^T   (shared K == V)
    mma_nt(Kt, Wv, KVt, 128, 960, 960, 960, 960, 960,
           128L * 960, FULL, 960L * 960, 7, 128L * 960, 1.f, 64);
    // KVtT [960][128] per batch (reuse dead Kt buffer)
    float* KVtT = Kt;
    {
        dim3 g(30, 4, 64);
        transpose_kvt<<<g, dim3(32, 8)>>>(KVt, KVtT);
    }

    const int Cqs[4] = {64, 128, 256, 512};
    long outOff = 0;
    for (int br = 0; br < 4; br++) {
        const int Cq = Cqs[br];
        // QtT[c,n] = sum_k Wq[c,k] * Q[n,k]   (NT: A=Wq head-indexed, B=Q slice)
        mma_nt(Wq[br], Q[br], QtT, Cq, 128, Cq, Cq, Cq, 128,
               (long)Cq * Cq, 7, 128L * Cq, FULL, (long)Cq * 128, 1.f, 64);
        // S[c,s] = inv_scale * sum_n QtT[c,n] * KVtT[s,n]   (NT)
        mma_nt(QtT, KVtT, S, Cq, 960, 128, 128, 128, 960,
               (long)Cq * 128, FULL, 960L * 128, FULL, (long)Cq * 960, inv_scale, 64);
        // InstanceNorm stats per (b,h), then row softmax in place
        inorm_stats<<<64, 1024>>>(S, stats, Cq * 960);
        inorm_softmax<<<64 * Cq, 256>>>(S, stats, Cq);
        // O[n,c] = sum_s KVt[n,s] * P[c,s]   (NT) -> lands contiguous as [B,N,Cq]
        mma_nt(KVt, S, O, 128, Cq, 960, 960, 960, Cq,
               128L * 960, FULL, (long)Cq * 960, FULL, 128L * Cq, 1.f, 64);
        // Y = O @ Wo^T  (single GEMM, M = B*N = 8192)
        mma_nt(O, Wo[br], out + outOff, 8192, Cq, Cq, Cq, Cq, Cq,
               0, 0, 0, 0, 0, 1.f, 1);
        outOff += 8192L * Cq;
    }
}